// round 8
// baseline (speedup 1.0000x reference)
#include <cuda_runtime.h>
#include <math.h>

#define NB 8
#define NG 512
#define NT 1024
#define NK 5
#define NC 3

#define TPB 256
#define TGRP (NT / TPB)          // 4 target-groups
#define NCHUNK 32
#define CHUNK_G (NG / NCHUNK)    // 16 grid rows per chunk

// replay-safe scratch: zero on entry, reset to zero before kernel exit
__device__ float        d_scratch[NB * NT * NC];
__device__ unsigned int d_count[NB * TGRP];

__device__ __forceinline__ float ex2f(float x) {
    float y;
    asm("ex2.approx.ftz.f32 %0, %1;" : "=f"(y) : "f"(x));
    return y;
}

__global__ __launch_bounds__(TPB)
void fused_kernel(const float* __restrict__ x_grid,
                  const float* __restrict__ h_grid,
                  const float* __restrict__ target_x,
                  const float* __restrict__ sigma,
                  const float* __restrict__ g_w,
                  const float* __restrict__ g_b,
                  float* __restrict__ out)
{
    __shared__ __align__(16) float rawh[CHUNK_G * NK * NC];  // 240
    __shared__ __align__(16) float rawx[CHUNK_G * NC];       // 48
    __shared__ __align__(16) float4 sxs[CHUNK_G];            // scaled coords
    __shared__ __align__(16) float4 shs[CHUNK_G];            // hsum
    __shared__ unsigned int s_last;

    const int tid    = threadIdx.x;
    const int tgroup = blockIdx.x;
    const int chunk  = blockIdx.y;
    const int b      = blockIdx.z;
    const int g0     = chunk * CHUNK_G;

    const float* xg = x_grid + (b * NG + g0) * NC;
    const float* hg = h_grid + (b * NG + g0) * NK * NC;

    // ---- coefficients (tiny, every thread; broadcast LDGs) ----
    float a2[NK][NC];
    #pragma unroll
    for (int k = 0; k < NK; k++)
        #pragma unroll
        for (int c = 0; c < NC; c++) {
            float s   = __expf(sigma[k * NC + c]) + 1e-6f;
            float inv = 1.0f / s;
            a2[k][c]  = -0.5f * 1.4426950408889634f * inv * inv;
        }
    bool uni = true;
    #pragma unroll
    for (int k = 1; k < NK; k++)
        #pragma unroll
        for (int c = 0; c < NC; c++)
            uni = uni && (a2[k][c] == a2[0][c]);

    // ---- target for this thread ----
    const int t     = tgroup * TPB + tid;
    const int obase = (b * NT + t) * NC;
    const float* tp = target_x + obase;

    float acc0 = 0.f, acc1 = 0.f, acc2 = 0.f;

    if (uni) {
        // ======== FAST PATH ========
        const float r0 = sqrtf(-a2[0][0]);
        const float r1 = sqrtf(-a2[0][1]);
        const float r2 = sqrtf(-a2[0][2]);

        // stage chunk: coalesced float4 copies (60 + 12 vectors)
        {
            const float4* hg4 = (const float4*)hg;   // 240 floats = 60 float4
            const float4* xg4 = (const float4*)xg;   // 48 floats  = 12 float4
            if (tid < 60)                 ((float4*)rawh)[tid] = hg4[tid];
            else if (tid >= 64 && tid < 76) ((float4*)rawx)[tid - 64] = xg4[tid - 64];
        }
        __syncthreads();

        // fold: 16 threads, one grid-row each (stride-15 LDS: conflict-free)
        if (tid < CHUNK_G) {
            const float* hp = rawh + tid * (NK * NC);
            float h0 = 0.f, h1 = 0.f, h2 = 0.f;
            #pragma unroll
            for (int k = 0; k < NK; k++) {
                const float w = g_w[k];
                h0 += w * hp[k * NC + 0];
                h1 += w * hp[k * NC + 1];
                h2 += w * hp[k * NC + 2];
            }
            const float* xp = rawx + tid * NC;
            sxs[tid] = make_float4(xp[0] * r0, xp[1] * r1, xp[2] * r2, 0.f);
            shs[tid] = make_float4(h0, h1, h2, 0.f);
        }

        const float t0 = tp[0] * r0;
        const float t1 = tp[1] * r1;
        const float t2 = tp[2] * r2;
        __syncthreads();

        #pragma unroll
        for (int gi = 0; gi < CHUNK_G; gi++) {
            const float4 xv = sxs[gi];   // broadcast LDS
            const float4 hv = shs[gi];
            float d;
            d = xv.x - t0; acc0 += hv.x * ex2f(d * (-d));
            d = xv.y - t1; acc1 += hv.y * ex2f(d * (-d));
            d = xv.z - t2; acc2 += hv.z * ex2f(d * (-d));
        }
    } else {
        // ======== GENERAL PATH: per-(k,c) scales, direct loads ========
        float gw[NK];
        #pragma unroll
        for (int k = 0; k < NK; k++) gw[k] = __ldg(&g_w[k]);

        const float t0 = tp[0], t1 = tp[1], t2 = tp[2];

        for (int gi = 0; gi < CHUNK_G; gi++) {
            const float* xp = xg + gi * NC;
            const float x0 = __ldg(&xp[0]), x1 = __ldg(&xp[1]), x2 = __ldg(&xp[2]);
            const float u0 = (x0 - t0) * (x0 - t0);
            const float u1 = (x1 - t1) * (x1 - t1);
            const float u2 = (x2 - t2) * (x2 - t2);
            const float* hp = hg + gi * NK * NC;
            #pragma unroll
            for (int k = 0; k < NK; k++) {
                acc0 += gw[k] * __ldg(&hp[k * NC + 0]) * ex2f(a2[k][0] * u0);
                acc1 += gw[k] * __ldg(&hp[k * NC + 1]) * ex2f(a2[k][1] * u1);
                acc2 += gw[k] * __ldg(&hp[k * NC + 2]) * ex2f(a2[k][2] * u2);
            }
        }
    }

    // ---- accumulate partials into scratch (fire-and-forget RED) ----
    atomicAdd(&d_scratch[obase + 0], acc0);
    atomicAdd(&d_scratch[obase + 1], acc1);
    atomicAdd(&d_scratch[obase + 2], acc2);

    // ---- last block per (b,tgroup) finalizes ----
    __syncthreads();
    if (tid == 0) {
        __threadfence();
        const int cidx = b * TGRP + tgroup;
        unsigned int v = atomicAdd(&d_count[cidx], 1u);
        s_last = (v == NCHUNK - 1) ? 1u : 0u;
    }
    __syncthreads();

    if (s_last) {
        const float bb = g_b[0];
        #pragma unroll
        for (int c = 0; c < NC; c++) {
            // atomic read guarantees visibility of all prior REDs
            float s = atomicAdd(&d_scratch[obase + c], 0.0f);
            out[obase + c] = s + bb;
            d_scratch[obase + c] = 0.0f;   // reset for next replay
        }
        if (tid == 0) {
            __threadfence();
            d_count[b * TGRP + tgroup] = 0u;   // reset counter
        }
    }
}

extern "C" void kernel_launch(void* const* d_in, const int* in_sizes, int n_in,
                              void* d_out, int out_size)
{
    const float* x_grid   = (const float*)d_in[0];  // (8, 512, 3)
    const float* h_grid   = (const float*)d_in[1];  // (8, 512, 5, 3)
    const float* target_x = (const float*)d_in[2];  // (8, 1024, 3)
    const float* sigma    = (const float*)d_in[3];  // (5, 3)
    const float* g_w      = (const float*)d_in[4];  // (1, 5)
    const float* g_b      = (const float*)d_in[5];  // (1,)
    float* out = (float*)d_out;                     // (8, 1024, 3)

    dim3 grid(TGRP, NCHUNK, NB);   // 4 x 32 x 8 = 1024 blocks
    fused_kernel<<<grid, TPB>>>(x_grid, h_grid, target_x, sigma, g_w, g_b, out);
}

// round 9
// speedup vs baseline: 1.2613x; 1.2613x over previous
#include <cuda_runtime.h>
#include <math.h>

#define NB 8
#define NG 512
#define NT 1024
#define NK 5
#define NC 3

#define TPB 256
#define TGRP (NT / TPB)          // 4 target-groups
#define NCHUNK 32
#define CHUNK_G (NG / NCHUNK)    // 16 grid rows per chunk

// replay-safe scratch: zero on entry, reset to zero before kernel exit
__device__ float        d_scratch[NB * NT * NC];
__device__ unsigned int d_count[NB * TGRP];

__device__ __forceinline__ float ex2f(float x) {
    float y;
    asm("ex2.approx.ftz.f32 %0, %1;" : "=f"(y) : "f"(x));
    return y;
}

__global__ __launch_bounds__(TPB)
void fused_kernel(const float* __restrict__ x_grid,
                  const float* __restrict__ h_grid,
                  const float* __restrict__ target_x,
                  const float* __restrict__ sigma,
                  const float* __restrict__ g_w,
                  const float* __restrict__ g_b,
                  float* __restrict__ out)
{
    __shared__ __align__(16) float rawh[CHUNK_G * NK * NC];  // 240 floats
    __shared__ __align__(16) float rawx[CHUNK_G * NC];       // 48 floats
    __shared__ __align__(16) float4 sxs[CHUNK_G];            // scaled coords
    __shared__ __align__(16) float4 shs[CHUNK_G];            // hsum
    __shared__ float s_r[NC];
    __shared__ int   s_uni;
    __shared__ int   s_last;

    const int tid    = threadIdx.x;
    const int warp   = tid >> 5;
    const int lane   = tid & 31;
    const int tgroup = blockIdx.x;
    const int chunk  = blockIdx.y;
    const int b      = blockIdx.z;
    const int g0     = chunk * CHUNK_G;

    const float* xg = x_grid + (b * NG + g0) * NC;
    const float* hg = h_grid + (b * NG + g0) * NK * NC;

    // ---- warp 0: lane-parallel coefficients (1 EX2 + 1 RCP warp-op) ----
    if (warp == 0) {
        float sv = 1.0f;
        if (lane < NK * NC) sv = __expf(sigma[lane]) + 1e-6f;   // lane = k*3+c
        // uniform iff every row k equals row 0 (per channel c = lane%3)
        float s0 = __shfl_sync(0xffffffffu, sv, lane % NC);
        bool ok  = (lane < NK * NC) ? (sv == s0) : true;
        unsigned m = __ballot_sync(0xffffffffu, ok);
        if (lane == 0) s_uni = (m == 0xffffffffu);
        if (lane < NC) s_r[lane] = 0.84932180028802f / sv;   // sqrt(0.5*log2(e))/s
    } else {
        // ---- warps 1..7: stage chunk (coalesced float4 copies) ----
        const int i = tid - 32;
        if (i < 60)                        ((float4*)rawh)[i] = ((const float4*)hg)[i];
        else if (tid >= 96 && tid < 108)   ((float4*)rawx)[tid - 96] = ((const float4*)xg)[tid - 96];
    }

    // ---- each thread: its target (independent of coefficients) ----
    const int t     = tgroup * TPB + tid;
    const int obase = (b * NT + t) * NC;
    const float* tp = target_x + obase;
    const float tr0 = tp[0], tr1 = tp[1], tr2 = tp[2];

    __syncthreads();

    float acc0 = 0.f, acc1 = 0.f, acc2 = 0.f;

    if (s_uni) {
        // ======== FAST PATH ========
        const float r0 = s_r[0], r1 = s_r[1], r2 = s_r[2];

        // fold: 16 threads (warp 0), one grid-row each
        if (tid < CHUNK_G) {
            const float* hp = rawh + tid * (NK * NC);
            float h0 = 0.f, h1 = 0.f, h2 = 0.f;
            #pragma unroll
            for (int k = 0; k < NK; k++) {
                const float w = g_w[k];
                h0 += w * hp[k * NC + 0];
                h1 += w * hp[k * NC + 1];
                h2 += w * hp[k * NC + 2];
            }
            const float* xp = rawx + tid * NC;
            sxs[tid] = make_float4(xp[0] * r0, xp[1] * r1, xp[2] * r2, 0.f);
            shs[tid] = make_float4(h0, h1, h2, 0.f);
        }

        const float t0 = tr0 * r0;
        const float t1 = tr1 * r1;
        const float t2 = tr2 * r2;
        __syncthreads();

        #pragma unroll
        for (int gi = 0; gi < CHUNK_G; gi++) {
            const float4 xv = sxs[gi];   // broadcast LDS.128
            const float4 hv = shs[gi];
            float d;
            d = xv.x - t0; acc0 += hv.x * ex2f(d * (-d));
            d = xv.y - t1; acc1 += hv.y * ex2f(d * (-d));
            d = xv.z - t2; acc2 += hv.z * ex2f(d * (-d));
        }
    } else {
        // ======== GENERAL PATH (cold): per-(k,c) scales, direct loads ========
        float a2[NK][NC];
        #pragma unroll
        for (int k = 0; k < NK; k++)
            #pragma unroll
            for (int c = 0; c < NC; c++) {
                float s   = __expf(sigma[k * NC + c]) + 1e-6f;
                float inv = 1.0f / s;
                a2[k][c]  = -0.5f * 1.4426950408889634f * inv * inv;
            }
        float gw[NK];
        #pragma unroll
        for (int k = 0; k < NK; k++) gw[k] = __ldg(&g_w[k]);

        for (int gi = 0; gi < CHUNK_G; gi++) {
            const float* xp = xg + gi * NC;
            const float x0 = __ldg(&xp[0]), x1 = __ldg(&xp[1]), x2 = __ldg(&xp[2]);
            const float u0 = (x0 - tr0) * (x0 - tr0);
            const float u1 = (x1 - tr1) * (x1 - tr1);
            const float u2 = (x2 - tr2) * (x2 - tr2);
            const float* hp = hg + gi * NK * NC;
            #pragma unroll
            for (int k = 0; k < NK; k++) {
                acc0 += gw[k] * __ldg(&hp[k * NC + 0]) * ex2f(a2[k][0] * u0);
                acc1 += gw[k] * __ldg(&hp[k * NC + 1]) * ex2f(a2[k][1] * u1);
                acc2 += gw[k] * __ldg(&hp[k * NC + 2]) * ex2f(a2[k][2] * u2);
            }
        }
    }

    // ---- accumulate partials (fire-and-forget RED) ----
    atomicAdd(&d_scratch[obase + 0], acc0);
    atomicAdd(&d_scratch[obase + 1], acc1);
    atomicAdd(&d_scratch[obase + 2], acc2);

    __threadfence();            // release: my REDs are globally visible
    __syncthreads();
    if (tid == 0) {
        unsigned int v = atomicAdd(&d_count[b * TGRP + tgroup], 1u);
        s_last = (v == NCHUNK - 1) ? 1 : 0;
    }
    __syncthreads();

    if (s_last) {
        __threadfence();        // acquire side
        const float bb = g_b[0];
        float s0 = __ldcg(&d_scratch[obase + 0]);
        float s1 = __ldcg(&d_scratch[obase + 1]);
        float s2 = __ldcg(&d_scratch[obase + 2]);
        out[obase + 0] = s0 + bb;
        out[obase + 1] = s1 + bb;
        out[obase + 2] = s2 + bb;
        // reset for next graph replay
        d_scratch[obase + 0] = 0.0f;
        d_scratch[obase + 1] = 0.0f;
        d_scratch[obase + 2] = 0.0f;
        if (tid == 0) d_count[b * TGRP + tgroup] = 0u;
    }
}

extern "C" void kernel_launch(void* const* d_in, const int* in_sizes, int n_in,
                              void* d_out, int out_size)
{
    const float* x_grid   = (const float*)d_in[0];  // (8, 512, 3)
    const float* h_grid   = (const float*)d_in[1];  // (8, 512, 5, 3)
    const float* target_x = (const float*)d_in[2];  // (8, 1024, 3)
    const float* sigma    = (const float*)d_in[3];  // (5, 3)
    const float* g_w      = (const float*)d_in[4];  // (1, 5)
    const float* g_b      = (const float*)d_in[5];  // (1,)
    float* out = (float*)d_out;                     // (8, 1024, 3)

    dim3 grid(TGRP, NCHUNK, NB);   // 4 x 32 x 8 = 1024 blocks
    fused_kernel<<<grid, TPB>>>(x_grid, h_grid, target_x, sigma, g_w, g_b, out);
}

// round 10
// speedup vs baseline: 1.2888x; 1.0218x over previous
#include <cuda_runtime.h>
#include <math.h>

#define NB 8
#define NG 512
#define NT 1024
#define NK 5
#define NC 3

#define PREP_TPB 256
#define MAIN_TPB 128
#define TGRP (NT / MAIN_TPB)     // 8 target-groups
#define NCHUNK 32
#define CHUNK_G (NG / NCHUNK)    // 16 grid rows per chunk

// device scratch (allocation-free per harness rules)
__device__ float4 d_xs[NB * NG];   // {r0*x0, r1*x1, r2*x2, 0}   (raw if !uni)
__device__ float4 d_hs[NB * NG];   // {hsum0, hsum1, hsum2, 0}
__device__ float4 d_ts[NB * NT];   // {r0*t0, r1*t1, r2*t2, 0}   (raw if !uni)
__device__ int    d_uni;

__device__ __forceinline__ float ex2f(float x) {
    float y;
    asm("ex2.approx.ftz.f32 %0, %1;" : "=f"(y) : "f"(x));
    return y;
}

// ---------------- prep: one item per thread, zero loops ----------------
__global__ __launch_bounds__(PREP_TPB)
void prep_kernel(const float* __restrict__ x_grid,
                 const float* __restrict__ h_grid,
                 const float* __restrict__ target_x,
                 const float* __restrict__ sigma,
                 const float* __restrict__ g_w,
                 const float* __restrict__ g_b,
                 float4* __restrict__ out4)
{
    const int gid = blockIdx.x * PREP_TPB + threadIdx.x;   // 0 .. 18431

    // coefficients (tiny, every thread)
    float a2[NK][NC];
    #pragma unroll
    for (int k = 0; k < NK; k++)
        #pragma unroll
        for (int c = 0; c < NC; c++) {
            float s   = __expf(sigma[k * NC + c]) + 1e-6f;
            float inv = 1.0f / s;
            a2[k][c]  = -0.5f * 1.4426950408889634f * inv * inv;
        }
    bool uni = true;
    #pragma unroll
    for (int k = 1; k < NK; k++)
        #pragma unroll
        for (int c = 0; c < NC; c++)
            uni = uni && (a2[k][c] == a2[0][c]);

    if (gid == 0) d_uni = uni ? 1 : 0;

    const float r0 = uni ? sqrtf(-a2[0][0]) : 1.0f;
    const float r1 = uni ? sqrtf(-a2[0][1]) : 1.0f;
    const float r2 = uni ? sqrtf(-a2[0][2]) : 1.0f;

    if (gid < NB * NG) {
        // per-(b,g): scaled coords + hsum
        const int i = gid;
        const float* xp = x_grid + i * NC;
        const float* hp = h_grid + i * NK * NC;
        float gw[NK];
        #pragma unroll
        for (int k = 0; k < NK; k++) gw[k] = g_w[k];
        float h0 = 0.f, h1 = 0.f, h2 = 0.f;
        #pragma unroll
        for (int k = 0; k < NK; k++) {
            h0 += gw[k] * hp[k * NC + 0];
            h1 += gw[k] * hp[k * NC + 1];
            h2 += gw[k] * hp[k * NC + 2];
        }
        d_xs[i] = make_float4(xp[0] * r0, xp[1] * r1, xp[2] * r2, 0.f);
        d_hs[i] = make_float4(h0, h1, h2, 0.f);
    } else if (gid < NB * NG + NB * NT) {
        // per-(b,t): scaled target
        const int i = gid - NB * NG;
        const float* tp = target_x + i * NC;
        d_ts[i] = make_float4(tp[0] * r0, tp[1] * r1, tp[2] * r2, 0.f);
    } else {
        // out := bias (vectorized): 24576 floats = 6144 float4
        const int i = gid - NB * NG - NB * NT;   // 0 .. 6143
        const float bb = g_b[0];
        out4[i] = make_float4(bb, bb, bb, bb);
    }
}

// ---------------- main: thread-per-target, 16-row g-chunk in smem ----------------
__global__ __launch_bounds__(MAIN_TPB)
void main_kernel(const float* __restrict__ x_grid,
                 const float* __restrict__ h_grid,
                 const float* __restrict__ g_w,
                 const float* __restrict__ sigma,
                 float* __restrict__ out)
{
    __shared__ float4 sxs[CHUNK_G];
    __shared__ float4 shs[CHUNK_G];

    const int tid    = threadIdx.x;
    const int tgroup = blockIdx.x;
    const int chunk  = blockIdx.y;
    const int b      = blockIdx.z;
    const int g0     = chunk * CHUNK_G;

    // stage chunk: 32 threads, one LDG.128 each
    if (tid < CHUNK_G)                sxs[tid]           = d_xs[b * NG + g0 + tid];
    else if (tid < 2 * CHUNK_G)       shs[tid - CHUNK_G] = d_hs[b * NG + g0 + tid - CHUNK_G];

    const int t     = tgroup * MAIN_TPB + tid;
    const int obase = (b * NT + t) * NC;
    const float4 tv = d_ts[b * NT + t];
    const int uni   = d_uni;

    __syncthreads();

    float acc0 = 0.f, acc1 = 0.f, acc2 = 0.f;

    if (uni) {
        #pragma unroll
        for (int gi = 0; gi < CHUNK_G; gi++) {
            const float4 xv = sxs[gi];   // broadcast LDS.128
            const float4 hv = shs[gi];
            float d;
            d = xv.x - tv.x; acc0 += hv.x * ex2f(d * (-d));
            d = xv.y - tv.y; acc1 += hv.y * ex2f(d * (-d));
            d = xv.z - tv.z; acc2 += hv.z * ex2f(d * (-d));
        }
    } else {
        // cold general path: per-(k,c) scales, direct loads (tv is raw here)
        float a2[NK][NC];
        #pragma unroll
        for (int k = 0; k < NK; k++)
            #pragma unroll
            for (int c = 0; c < NC; c++) {
                float s   = __expf(sigma[k * NC + c]) + 1e-6f;
                float inv = 1.0f / s;
                a2[k][c]  = -0.5f * 1.4426950408889634f * inv * inv;
            }
        float gw[NK];
        #pragma unroll
        for (int k = 0; k < NK; k++) gw[k] = __ldg(&g_w[k]);

        const float* xg = x_grid + (b * NG + g0) * NC;
        const float* hg = h_grid + (b * NG + g0) * NK * NC;
        for (int gi = 0; gi < CHUNK_G; gi++) {
            const float* xp = xg + gi * NC;
            const float x0 = __ldg(&xp[0]), x1 = __ldg(&xp[1]), x2 = __ldg(&xp[2]);
            const float u0 = (x0 - tv.x) * (x0 - tv.x);
            const float u1 = (x1 - tv.y) * (x1 - tv.y);
            const float u2 = (x2 - tv.z) * (x2 - tv.z);
            const float* hp = hg + gi * NK * NC;
            #pragma unroll
            for (int k = 0; k < NK; k++) {
                acc0 += gw[k] * __ldg(&hp[k * NC + 0]) * ex2f(a2[k][0] * u0);
                acc1 += gw[k] * __ldg(&hp[k * NC + 1]) * ex2f(a2[k][1] * u1);
                acc2 += gw[k] * __ldg(&hp[k * NC + 2]) * ex2f(a2[k][2] * u2);
            }
        }
    }

    // fire-and-forget REDs into bias-initialized out
    atomicAdd(&out[obase + 0], acc0);
    atomicAdd(&out[obase + 1], acc1);
    atomicAdd(&out[obase + 2], acc2);
}

extern "C" void kernel_launch(void* const* d_in, const int* in_sizes, int n_in,
                              void* d_out, int out_size)
{
    const float* x_grid   = (const float*)d_in[0];  // (8, 512, 3)
    const float* h_grid   = (const float*)d_in[1];  // (8, 512, 5, 3)
    const float* target_x = (const float*)d_in[2];  // (8, 1024, 3)
    const float* sigma    = (const float*)d_in[3];  // (5, 3)
    const float* g_w      = (const float*)d_in[4];  // (1, 5)
    const float* g_b      = (const float*)d_in[5];  // (1,)
    float* out = (float*)d_out;                     // (8, 1024, 3)

    // 72 blocks * 256 = 18432 = 4096 (b,g) + 8192 (b,t) + 6144 out-init float4
    prep_kernel<<<72, PREP_TPB>>>(x_grid, h_grid, target_x, sigma, g_w, g_b,
                                  (float4*)out);

    dim3 grid(TGRP, NCHUNK, NB);   // 8 x 32 x 8 = 2048 blocks of 128
    main_kernel<<<grid, MAIN_TPB>>>(x_grid, h_grid, g_w, sigma, out);
}

// round 12
// speedup vs baseline: 1.3721x; 1.0646x over previous
#include <cuda_runtime.h>
#include <math.h>

#define NB 8
#define NG 512
#define NT 1024
#define NK 5
#define NC 3

#define PREP_TPB 256
#define MAIN_TPB 128
#define TGRP (NT / MAIN_TPB)     // 8 target-groups
#define NCHUNK 16
#define CHUNK_G (NG / NCHUNK)    // 32 grid rows per chunk

// device scratch (allocation-free per harness rules)
__device__ float4 d_p1[NB * NG];   // {2x0', -x0'^2, 2x1', -x1'^2}
__device__ float4 d_p2[NB * NG];   // {2x2', -x2'^2, h0, h1}
__device__ float  d_p3[NB * NG];   // h2
__device__ float4 d_ts[NB * NT];   // {t0', t1', t2', 0}  (raw if !uni)
__device__ int    d_uni;

__device__ __forceinline__ float ex2f(float x) {
    float y;
    asm("ex2.approx.ftz.f32 %0, %1;" : "=f"(y) : "f"(x));
    return y;
}

// ---------------- prep ----------------
// blocks 0..15  : fold 256 (b,g)-rows each (coalesced smem staging)
// blocks 16..47 : targets (one per thread)
// blocks 48..71 : out := bias (float4 stores)
__global__ __launch_bounds__(PREP_TPB)
void prep_kernel(const float* __restrict__ x_grid,
                 const float* __restrict__ h_grid,
                 const float* __restrict__ target_x,
                 const float* __restrict__ sigma,
                 const float* __restrict__ g_w,
                 const float* __restrict__ g_b,
                 float4* __restrict__ out4)
{
    __shared__ __align__(16) float sh[256 * NK * NC];   // 3840 floats = 15KB

    const int tid = threadIdx.x;
    const int blk = blockIdx.x;

    // coefficients (tiny, every thread)
    float a2[NK][NC];
    #pragma unroll
    for (int k = 0; k < NK; k++)
        #pragma unroll
        for (int c = 0; c < NC; c++) {
            float s   = __expf(sigma[k * NC + c]) + 1e-6f;
            float inv = 1.0f / s;
            a2[k][c]  = -0.5f * 1.4426950408889634f * inv * inv;
        }
    bool uni = true;
    #pragma unroll
    for (int k = 1; k < NK; k++)
        #pragma unroll
        for (int c = 0; c < NC; c++)
            uni = uni && (a2[k][c] == a2[0][c]);

    if (blk == 0 && tid == 0) d_uni = uni ? 1 : 0;

    const float r0 = uni ? sqrtf(-a2[0][0]) : 1.0f;
    const float r1 = uni ? sqrtf(-a2[0][1]) : 1.0f;
    const float r2 = uni ? sqrtf(-a2[0][2]) : 1.0f;

    if (blk < 16) {
        // ---- fold: rows r0b .. r0b+255 ----
        const int rbase = blk * 256;
        // coalesced float4 copy: 256 rows * 15 floats = 960 float4 (16B-aligned)
        const float4* hg4 = (const float4*)(h_grid) + rbase * (NK * NC) / 4;
        #pragma unroll
        for (int i = 0; i < 960 / 256 + 1; i++) {
            int idx = tid + i * PREP_TPB;
            if (idx < 960) ((float4*)sh)[idx] = hg4[idx];
        }
        __syncthreads();

        const int row = rbase + tid;
        const float* hp = sh + tid * (NK * NC);   // stride 15: conflict-free
        float gw[NK];
        #pragma unroll
        for (int k = 0; k < NK; k++) gw[k] = g_w[k];
        float h0 = 0.f, h1 = 0.f, h2 = 0.f;
        #pragma unroll
        for (int k = 0; k < NK; k++) {
            h0 += gw[k] * hp[k * NC + 0];
            h1 += gw[k] * hp[k * NC + 1];
            h2 += gw[k] * hp[k * NC + 2];
        }
        const float* xp = x_grid + row * NC;
        const float sx0 = xp[0] * r0, sx1 = xp[1] * r1, sx2 = xp[2] * r2;
        d_p1[row] = make_float4(2.f * sx0, -sx0 * sx0, 2.f * sx1, -sx1 * sx1);
        d_p2[row] = make_float4(2.f * sx2, -sx2 * sx2, h0, h1);
        d_p3[row] = h2;
    } else if (blk < 48) {
        // ---- targets ----
        const int i = (blk - 16) * PREP_TPB + tid;   // 0..8191
        const float* tp = target_x + i * NC;
        d_ts[i] = make_float4(tp[0] * r0, tp[1] * r1, tp[2] * r2, 0.f);
    } else {
        // ---- out := bias ----
        const int i = (blk - 48) * PREP_TPB + tid;   // 0..6143
        const float bb = g_b[0];
        out4[i] = make_float4(bb, bb, bb, bb);
    }
}

// ---------------- main: thread-per-target, 32-row g-chunk ----------------
__global__ __launch_bounds__(MAIN_TPB)
void main_kernel(const float* __restrict__ x_grid,
                 const float* __restrict__ h_grid,
                 const float* __restrict__ g_w,
                 const float* __restrict__ sigma,
                 float* __restrict__ out)
{
    __shared__ __align__(16) float4 s1[CHUNK_G];
    __shared__ __align__(16) float4 s2[CHUNK_G];
    __shared__ __align__(16) float  s3[CHUNK_G];

    const int tid    = threadIdx.x;
    const int tgroup = blockIdx.x;
    const int chunk  = blockIdx.y;
    const int b      = blockIdx.z;
    const int g0     = chunk * CHUNK_G;
    const int gbase  = b * NG + g0;

    // stage: 72 threads, one LDG.128 each
    if (tid < CHUNK_G)                 s1[tid]           = d_p1[gbase + tid];
    else if (tid < 2 * CHUNK_G)        s2[tid - CHUNK_G] = d_p2[gbase + tid - CHUNK_G];
    else if (tid < 2 * CHUNK_G + CHUNK_G / 4)
        ((float4*)s3)[tid - 2 * CHUNK_G] = ((const float4*)(d_p3 + gbase))[tid - 2 * CHUNK_G];

    const int t     = tgroup * MAIN_TPB + tid;
    const int obase = (b * NT + t) * NC;
    const float4 tv = d_ts[b * NT + t];
    const int uni   = d_uni;

    __syncthreads();

    float acc0 = 0.f, acc1 = 0.f, acc2 = 0.f;

    if (uni) {
        #pragma unroll
        for (int gi = 0; gi < CHUNK_G; gi++) {
            const float4 A = s1[gi];   // {2x0, -x0^2, 2x1, -x1^2}
            const float4 B = s2[gi];   // {2x2, -x2^2, h0, h1}
            const float  h2 = s3[gi];
            acc0 += B.z * ex2f(fmaf(A.x, tv.x, A.y));
            acc1 += B.w * ex2f(fmaf(A.z, tv.y, A.w));
            acc2 += h2  * ex2f(fmaf(B.x, tv.z, B.y));
        }
        // factor 2^(-t'^2) applied once per channel
        acc0 *= ex2f(-tv.x * tv.x);
        acc1 *= ex2f(-tv.y * tv.y);
        acc2 *= ex2f(-tv.z * tv.z);
    } else {
        // cold general path: per-(k,c) scales, direct loads (tv is raw here)
        float a2[NK][NC];
        #pragma unroll
        for (int k = 0; k < NK; k++)
            #pragma unroll
            for (int c = 0; c < NC; c++) {
                float s   = __expf(sigma[k * NC + c]) + 1e-6f;
                float inv = 1.0f / s;
                a2[k][c]  = -0.5f * 1.4426950408889634f * inv * inv;
            }
        float gw[NK];
        #pragma unroll
        for (int k = 0; k < NK; k++) gw[k] = __ldg(&g_w[k]);

        const float* xg = x_grid + gbase * NC;
        const float* hg = h_grid + gbase * NK * NC;
        for (int gi = 0; gi < CHUNK_G; gi++) {
            const float* xp = xg + gi * NC;
            const float x0 = __ldg(&xp[0]), x1 = __ldg(&xp[1]), x2 = __ldg(&xp[2]);
            const float u0 = (x0 - tv.x) * (x0 - tv.x);
            const float u1 = (x1 - tv.y) * (x1 - tv.y);
            const float u2 = (x2 - tv.z) * (x2 - tv.z);
            const float* hp = hg + gi * NK * NC;
            #pragma unroll
            for (int k = 0; k < NK; k++) {
                acc0 += gw[k] * __ldg(&hp[k * NC + 0]) * ex2f(a2[k][0] * u0);
                acc1 += gw[k] * __ldg(&hp[k * NC + 1]) * ex2f(a2[k][1] * u1);
                acc2 += gw[k] * __ldg(&hp[k * NC + 2]) * ex2f(a2[k][2] * u2);
            }
        }
    }

    // fire-and-forget REDs into bias-initialized out
    atomicAdd(&out[obase + 0], acc0);
    atomicAdd(&out[obase + 1], acc1);
    atomicAdd(&out[obase + 2], acc2);
}

extern "C" void kernel_launch(void* const* d_in, const int* in_sizes, int n_in,
                              void* d_out, int out_size)
{
    const float* x_grid   = (const float*)d_in[0];  // (8, 512, 3)
    const float* h_grid   = (const float*)d_in[1];  // (8, 512, 5, 3)
    const float* target_x = (const float*)d_in[2];  // (8, 1024, 3)
    const float* sigma    = (const float*)d_in[3];  // (5, 3)
    const float* g_w      = (const float*)d_in[4];  // (1, 5)
    const float* g_b      = (const float*)d_in[5];  // (1,)
    float* out = (float*)d_out;                     // (8, 1024, 3)

    // 72 blocks: 16 fold + 32 target + 24 out-init
    prep_kernel<<<72, PREP_TPB>>>(x_grid, h_grid, target_x, sigma, g_w, g_b,
                                  (float4*)out);

    dim3 grid(TGRP, NCHUNK, NB);   // 8 x 16 x 8 = 1024 blocks of 128
    main_kernel<<<grid, MAIN_TPB>>>(x_grid, h_grid, g_w, sigma, out);
}